// round 9
// baseline (speedup 1.0000x reference)
#include <cuda_runtime.h>
#include <cstdint>
#include <cstddef>

// ---------------- problem constants ----------------
#define NTOKENS 8192
#define TOPK    2
#define NEXP    8
#define KDIM    1024
#define NDIM    1024
#define M_OUT   (NTOKENS * TOPK)          // 16384 dispatched rows

#define TILE_M  128
#define TILE_N  128
#define CHUNK_K 32                        // fp32/tf32 elems per K chunk
#define NUM_CHUNKS (KDIM / CHUNK_K)       // 32
#define N_TILES (NDIM / TILE_N)           // 8
#define MAX_ROW_TILES 136                 // 16384/128 + NEXP slack
#define THREADS 128
#define STAGES  4                         // A-only stages now

// smem: A tile only. padded row stride 36 floats -> conflict-free LDS.128
#define A_STRIDE 36
#define A_STAGE_BYTES (TILE_M * A_STRIDE * 4)   // 18432
#define SM_TOK    0                              // 128 ints
#define SM_STAGE0 512
#define SMEM_ALLOC (SM_STAGE0 + STAGES * A_STAGE_BYTES)  // 74240 -> 2 CTAs/SM

// ---------------- PTX helpers (base sm_80+ ISA; harness targets sm_103 base) -
__device__ __forceinline__ uint32_t smem_to_u32(const void* p) {
    uint32_t a;
    asm("{ .reg .u64 t; cvta.to.shared.u64 t, %1; cvt.u32.u64 %0, t; }" : "=r"(a) : "l"(p));
    return a;
}
#define CP_ASYNC16(dst_u32, src_ptr) \
    asm volatile("cp.async.cg.shared.global [%0], [%1], 16;" :: "r"(dst_u32), "l"(src_ptr))
#define CP_COMMIT() asm volatile("cp.async.commit_group;" ::: "memory")
#define CP_WAIT_2() asm volatile("cp.async.wait_group 2;" ::: "memory")

__device__ __forceinline__ uint32_t f2tf32(float f) {
    uint32_t r;
    asm("cvt.rna.tf32.f32 %0, %1;" : "=r"(r) : "f"(f));
    return r;
}

// mma.sync m16n8k8 tf32, fp32 accumulate (operands already tf32-rounded bits)
__device__ __forceinline__ void mma_tf32(float* c, uint32_t a0, uint32_t a1, uint32_t a2,
                                         uint32_t a3, uint32_t b0, uint32_t b1) {
    asm volatile(
        "mma.sync.aligned.m16n8k8.row.col.f32.tf32.tf32.f32 "
        "{%0,%1,%2,%3}, {%4,%5,%6,%7}, {%8,%9}, {%0,%1,%2,%3};"
        : "+f"(c[0]), "+f"(c[1]), "+f"(c[2]), "+f"(c[3])
        : "r"(a0), "r"(a1), "r"(a2), "r"(a3), "r"(b0), "r"(b1));
}

// ---------------- static device scratch (allocation-free rule) --------------
__device__ float g_xt[(size_t)NTOKENS * KDIM];          // tf32-rounded, row-packed
// B fragment-major: tile t = (e*128 + n8)*32 + kc holds an 8x32 chunk as
// 2 kp-halves of 512B; within a half, lane L's 16B piece at L*16.
__device__ float g_wb[(size_t)NEXP * NDIM * KDIM];
__device__ int g_token_of_row[M_OUT];
__device__ int g_tile_expert[MAX_ROW_TILES];
__device__ int g_tile_row0[MAX_ROW_TILES];
__device__ int g_tile_rows[MAX_ROW_TILES];
__device__ int g_num_tiles;

// ---------------- setup kernels ---------------------------------------------
// Row-pack permutation (both operands): dst pos p = 8*lc + 2*kf + pair
//   <- src j = kf*8 + lc + 4*pair  (kf = k fragment 0..3, pair = k&4-half)
// x: store packed rows linearly (consumed via cp.async + LDS.128).
// w: store fragment-major per 8-row x 32-col tile (consumed via coalesced LDG.128):
//   piece (kp, lr, lc) at float offset kp*128 + lr*16 + lc*4 within the 256-float tile.
__global__ void k_round(const float* __restrict__ x, const float* __restrict__ w) {
    const size_t HALF_CHUNKS = (size_t)NTOKENS * KDIM / 32;   // == NEXP*NDIM*KDIM/32
    size_t g = (size_t)blockIdx.x * blockDim.x + threadIdx.x;
    const bool is_w = (g >= HALF_CHUNKS);
    if (g >= 2 * HALF_CHUNKS) return;
    if (is_w) g -= HALF_CHUNKS;
    const float* src = is_w ? w : x;
    const size_t base = g * 32;

    float v[32];
#pragma unroll
    for (int q = 0; q < 8; q++)
        *reinterpret_cast<float4*>(v + q * 4) = *reinterpret_cast<const float4*>(src + base + q * 4);
    uint32_t o[32];
#pragma unroll
    for (int p = 0; p < 32; p++) {
        const int lc = p >> 3, kf = (p & 7) >> 1, pair = p & 1;
        o[p] = f2tf32(v[kf * 8 + lc + 4 * pair]);
    }

    if (!is_w) {
#pragma unroll
        for (int q = 0; q < 8; q++)
            *reinterpret_cast<uint4*>(g_xt + base + q * 4) =
                make_uint4(o[q * 4], o[q * 4 + 1], o[q * 4 + 2], o[q * 4 + 3]);
    } else {
        // g indexes w chunks: n_row = (g*32)/KDIM within expert block, kc = chunk col
        const uint32_t row = (uint32_t)(base / KDIM);          // e*1024 + n
        const uint32_t kc  = (uint32_t)((base % KDIM) / 32);
        const uint32_t n8  = row >> 3;                          // (e*1024+n)/8 = e*128 + n/8
        const uint32_t lr  = row & 7;
        float* tile = g_wb + ((size_t)n8 * 32 + kc) * 256;
#pragma unroll
        for (int kp = 0; kp < 2; kp++)
#pragma unroll
            for (int lc = 0; lc < 4; lc++) {
                const int p = lc * 8 + kp * 4;
                *reinterpret_cast<uint4*>(tile + kp * 128 + lr * 16 + lc * 4) =
                    make_uint4(o[p], o[p + 1], o[p + 2], o[p + 3]);
            }
    }
}

__global__ void k_token(const int* __restrict__ scatter) {
    int i = blockIdx.x * blockDim.x + threadIdx.x;
    if (i < M_OUT) g_token_of_row[scatter[i]] = i / TOPK;
}

__global__ void k_tiles(const int* __restrict__ splits) {
    if (threadIdx.x != 0 || blockIdx.x != 0) return;
    int off = 0, t = 0;
    for (int e = 0; e < NEXP; e++) {
        int sc = splits[e];
        for (int m0 = 0; m0 < sc; m0 += TILE_M) {
            g_tile_expert[t] = e;
            g_tile_row0[t]   = off + m0;
            int rr = sc - m0;
            g_tile_rows[t]   = rr < TILE_M ? rr : TILE_M;
            t++;
        }
        off += sc;
    }
    g_num_tiles = t;
}

// ---------------- main grouped-GEMM kernel -----------------------------------
// 128 threads = 4 warps, warp grid 2x2, warp tile 64x64. 2 CTAs/SM.
// A: cp.async -> smem -> LDS.128 fragments.  B: direct coalesced LDG.128 fragments.
__global__ void __launch_bounds__(THREADS, 2) moe_gemm_kernel(float* __restrict__ out) {
    extern __shared__ char smem[];
    const uint32_t sbase = smem_to_u32(smem);

    const int row_tile = blockIdx.x;
    if (row_tile >= g_num_tiles) return;
    const int e    = g_tile_expert[row_tile];
    const int row0 = g_tile_row0[row_tile];
    const int rows = g_tile_rows[row_tile];
    const int n0   = blockIdx.y * TILE_N;

    const int tid  = threadIdx.x;
    const int wid  = tid >> 5;
    const int lane = tid & 31;
    const int lr = lane >> 2;         // 0..7  fragment row
    const int lc = lane & 3;          // 0..3  fragment col group
    const int wm = (wid >> 1) * 64;   // warp M offset
    const int wn = (wid & 1) * 64;    // warp N offset

    int* s_tok = reinterpret_cast<int*>(smem + SM_TOK);
    if (tid < TILE_M) {
        int r = (tid < rows) ? (row0 + tid) : row0;
        s_tok[tid] = g_token_of_row[r];
    }
    __syncthreads();

    // ---- A cp.async plan: 16 rows per pass, 8 passes ----
    const int seg   = tid & 7;          // 16B piece of the 128B row-chunk
    const int rbase = tid >> 3;         // 0..15
    uint32_t a_src[8];
#pragma unroll
    for (int j = 0; j < 8; j++)
        a_src[j] = (uint32_t)s_tok[rbase + 16 * j] * KDIM + seg * 4;
    const uint32_t d0 = (uint32_t)rbase * (A_STRIDE * 4) + seg * 16;

    auto load_stage = [&](int ch, int s) {
        const uint32_t abase = sbase + SM_STAGE0 + s * A_STAGE_BYTES;
        const uint32_t koff = (uint32_t)ch * CHUNK_K;
#pragma unroll
        for (int j = 0; j < 8; j++)
            CP_ASYNC16(abase + d0 + j * (16 * A_STRIDE * 4), g_xt + a_src[j] + koff);
    };

    // ---- B fragment base: tile (e*128 + n8) for this warp's column block ----
    // per-(nf,ch,kp) offsets: nf*32*256 + ch*256 + kp*128; per-lane piece lane*4.
    const float* wb = g_wb + ((size_t)((uint32_t)e * 128u + (uint32_t)((n0 + wn) >> 3)) * 32u) * 256u
                      + lane * 4;

    // ---- accumulators: warp tile 64x64 -> 4 mf x 8 nf x 4 regs = 128 ----
    float acc[4][8][4];
#pragma unroll
    for (int mf = 0; mf < 4; mf++)
#pragma unroll
        for (int nf = 0; nf < 8; nf++)
#pragma unroll
            for (int r = 0; r < 4; r++) acc[mf][nf][r] = 0.f;

    load_stage(0, 0); CP_COMMIT();
    load_stage(1, 1); CP_COMMIT();
    load_stage(2, 2); CP_COMMIT();

    const float* As0 = reinterpret_cast<const float*>(smem + SM_STAGE0);

#pragma unroll 1
    for (int ch = 0; ch < NUM_CHUNKS; ch++) {
        CP_WAIT_2();
        __syncthreads();

        if (ch + 3 < NUM_CHUNKS) load_stage(ch + 3, (ch + 3) % STAGES);
        CP_COMMIT();

        const int s = ch % STAGES;
        const float* As = As0 + (size_t)s * (A_STAGE_BYTES / 4);
        const float* wbc = wb + (size_t)ch * 256;

#pragma unroll
        for (int kp = 0; kp < 2; kp++) {
            // B fragments: one coalesced 512B LDG.128 per nf
            uint4 qb[8];
#pragma unroll
            for (int nf = 0; nf < 8; nf++)
                qb[nf] = *reinterpret_cast<const uint4*>(wbc + nf * (32 * 256) + kp * 128);

            const int fo = lc * 8 + kp * 4;      // packed-row float offset
            uint4 qa[4][2];
#pragma unroll
            for (int mf = 0; mf < 4; mf++) {
                const int r = wm + mf * 16 + lr;
                qa[mf][0] = *reinterpret_cast<const uint4*>(As + r * A_STRIDE + fo);
                qa[mf][1] = *reinterpret_cast<const uint4*>(As + (r + 8) * A_STRIDE + fo);
            }

            // kf = 2kp (.x/.y) then kf = 2kp+1 (.z/.w): 32 independent MMAs
            // between accumulator reuses.
#pragma unroll
            for (int mf = 0; mf < 4; mf++)
#pragma unroll
                for (int nf = 0; nf < 8; nf++)
                    mma_tf32(acc[mf][nf], qa[mf][0].x, qa[mf][1].x, qa[mf][0].y, qa[mf][1].y,
                             qb[nf].x, qb[nf].y);
#pragma unroll
            for (int mf = 0; mf < 4; mf++)
#pragma unroll
                for (int nf = 0; nf < 8; nf++)
                    mma_tf32(acc[mf][nf], qa[mf][0].z, qa[mf][1].z, qa[mf][0].w, qa[mf][1].w,
                             qb[nf].z, qb[nf].w);
        }
    }

    // ---- epilogue: direct float2 stores, mask rows beyond this tile ----
#pragma unroll
    for (int mf = 0; mf < 4; mf++) {
        const int r_lo = wm + mf * 16 + lr;
        const int r_hi = r_lo + 8;
        const bool v_lo = (r_lo < rows);
        const bool v_hi = (r_hi < rows);
        float* o_lo = out + (size_t)(row0 + r_lo) * NDIM + n0;
        float* o_hi = out + (size_t)(row0 + r_hi) * NDIM + n0;
#pragma unroll
        for (int nf = 0; nf < 8; nf++) {
            const int col = wn + nf * 8 + 2 * lc;
            if (v_lo) *reinterpret_cast<float2*>(o_lo + col) =
                make_float2(acc[mf][nf][0], acc[mf][nf][1]);
            if (v_hi) *reinterpret_cast<float2*>(o_hi + col) =
                make_float2(acc[mf][nf][2], acc[mf][nf][3]);
        }
    }
}

// ---------------- launch ------------------------------------------------------
extern "C" void kernel_launch(void* const* d_in, const int* in_sizes, int n_in,
                              void* d_out, int out_size) {
    const float* x       = (const float*)d_in[0];
    const float* w       = (const float*)d_in[1];
    const int*   scatter = (const int*)d_in[2];
    const int*   splits  = (const int*)d_in[3];
    float*       out     = (float*)d_out;
    (void)in_sizes; (void)n_in; (void)out_size;

    cudaFuncSetAttribute(moe_gemm_kernel, cudaFuncAttributeMaxDynamicSharedMemorySize, SMEM_ALLOC);

    const size_t total_chunks = ((size_t)NTOKENS * KDIM + (size_t)NEXP * NDIM * KDIM) / 32;
    k_round<<<(int)((total_chunks + 255) / 256), 256>>>(x, w);
    k_token<<<(M_OUT + 255) / 256, 256>>>(scatter);
    k_tiles<<<1, 32>>>(splits);

    dim3 grid(MAX_ROW_TILES, N_TILES);
    moe_gemm_kernel<<<grid, THREADS, SMEM_ALLOC>>>(out);
}

// round 11
// speedup vs baseline: 2.1182x; 2.1182x over previous
#include <cuda_runtime.h>
#include <cuda_fp16.h>
#include <cstdint>
#include <cstddef>

// ---------------- problem constants ----------------
#define NTOKENS 8192
#define TOPK    2
#define NEXP    8
#define KDIM    1024
#define NDIM    1024
#define M_OUT   (NTOKENS * TOPK)          // 16384 dispatched rows

#define TILE_M  128
#define TILE_N  128
#define CHUNK_K 64                        // fp16 elems per K chunk = 128B/row
#define NUM_CHUNKS (KDIM / CHUNK_K)       // 16
#define N_TILES (NDIM / TILE_N)           // 8
#define MAX_ROW_TILES 136                 // 16384/128 + NEXP slack
#define THREADS 128
#define STAGES  3

// smem rows padded to 144B -> ldmatrix / cp.async conflict-free
#define ROW_BYTES   144
#define A_STAGE_BYTES (TILE_M * ROW_BYTES)      // 18432
#define B_STAGE_BYTES (TILE_N * ROW_BYTES)      // 18432
#define STAGE_BYTES   (A_STAGE_BYTES + B_STAGE_BYTES)  // 36864
#define SM_TOK    0                              // 128 ints
#define SM_STAGE0 512
#define SMEM_ALLOC (SM_STAGE0 + STAGES * STAGE_BYTES)  // 111104 -> 2 CTAs/SM

// ---------------- PTX helpers (base sm_75/80 ISA; harness targets sm_103 base)
__device__ __forceinline__ uint32_t smem_to_u32(const void* p) {
    uint32_t a;
    asm("{ .reg .u64 t; cvta.to.shared.u64 t, %1; cvt.u32.u64 %0, t; }" : "=r"(a) : "l"(p));
    return a;
}
#define CP_ASYNC16(dst_u32, src_ptr) \
    asm volatile("cp.async.cg.shared.global [%0], [%1], 16;" :: "r"(dst_u32), "l"(src_ptr))
#define CP_COMMIT() asm volatile("cp.async.commit_group;" ::: "memory")
#define CP_WAIT_1() asm volatile("cp.async.wait_group 1;" ::: "memory")

// ldmatrix x4: 4 8x8 b16 tiles; per-lane row address in 'addr'
#define LDMATRIX_X4(r, addr) \
    asm volatile("ldmatrix.sync.aligned.m8n8.x4.shared.b16 {%0,%1,%2,%3}, [%4];" \
                 : "=r"((r)[0]), "=r"((r)[1]), "=r"((r)[2]), "=r"((r)[3]) : "r"(addr))

// mma m16n8k16 fp16 in, fp32 accumulate
__device__ __forceinline__ void mma_f16(float* c, const uint32_t* a, uint32_t b0, uint32_t b1) {
    asm volatile(
        "mma.sync.aligned.m16n8k16.row.col.f32.f16.f16.f32 "
        "{%0,%1,%2,%3}, {%4,%5,%6,%7}, {%8,%9}, {%0,%1,%2,%3};"
        : "+f"(c[0]), "+f"(c[1]), "+f"(c[2]), "+f"(c[3])
        : "r"(a[0]), "r"(a[1]), "r"(a[2]), "r"(a[3]), "r"(b0), "r"(b1));
}

// ---------------- static device scratch (allocation-free rule) --------------
__device__ __half g_xh[(size_t)NTOKENS * KDIM];          // fp16 x, row-major
__device__ __half g_wh[(size_t)NEXP * NDIM * KDIM];      // fp16 W, [e][n][k]
__device__ int g_token_of_row[M_OUT];
__device__ int g_tile_expert[MAX_ROW_TILES];
__device__ int g_tile_row0[MAX_ROW_TILES];
__device__ int g_tile_rows[MAX_ROW_TILES];
__device__ int g_num_tiles;

// ---------------- setup kernels ---------------------------------------------
__device__ __forceinline__ uint32_t pack2(float a, float b) {
    __half2 h = __floats2half2_rn(a, b);
    uint32_t u;
    memcpy(&u, &h, 4);
    return u;
}

__global__ void k_half(const float* __restrict__ x, const float* __restrict__ w) {
    const size_t HALF_GROUPS = (size_t)NTOKENS * KDIM / 8;   // == NEXP*NDIM*KDIM/8
    size_t g = (size_t)blockIdx.x * blockDim.x + threadIdx.x;
    const float* src;
    __half* dst;
    if (g < HALF_GROUPS)          { src = x; dst = g_xh; }
    else if (g < 2 * HALF_GROUPS) { src = w; dst = g_wh; g -= HALF_GROUPS; }
    else return;
    const size_t base = g * 8;
    float4 lo = *reinterpret_cast<const float4*>(src + base);
    float4 hi = *reinterpret_cast<const float4*>(src + base + 4);
    *reinterpret_cast<uint4*>(dst + base) =
        make_uint4(pack2(lo.x, lo.y), pack2(lo.z, lo.w), pack2(hi.x, hi.y), pack2(hi.z, hi.w));
}

__global__ void k_token(const int* __restrict__ scatter) {
    int i = blockIdx.x * blockDim.x + threadIdx.x;
    if (i < M_OUT) g_token_of_row[scatter[i]] = i / TOPK;
}

__global__ void k_tiles(const int* __restrict__ splits) {
    if (threadIdx.x != 0 || blockIdx.x != 0) return;
    int off = 0, t = 0;
    for (int e = 0; e < NEXP; e++) {
        int sc = splits[e];
        for (int m0 = 0; m0 < sc; m0 += TILE_M) {
            g_tile_expert[t] = e;
            g_tile_row0[t]   = off + m0;
            int rr = sc - m0;
            g_tile_rows[t]   = rr < TILE_M ? rr : TILE_M;
            t++;
        }
        off += sc;
    }
    g_num_tiles = t;
}

// ---------------- main grouped-GEMM kernel -----------------------------------
// 128 threads = 4 warps, warp grid 2x2, warp tile 64x64, fp16 m16n8k16. 2 CTAs/SM.
__global__ void __launch_bounds__(THREADS, 2) moe_gemm_kernel(float* __restrict__ out) {
    extern __shared__ char smem[];
    const uint32_t sbase = smem_to_u32(smem);

    const int row_tile = blockIdx.x;
    if (row_tile >= g_num_tiles) return;
    const int e    = g_tile_expert[row_tile];
    const int row0 = g_tile_row0[row_tile];
    const int rows = g_tile_rows[row_tile];
    const int n0   = blockIdx.y * TILE_N;

    const int tid  = threadIdx.x;
    const int wid  = tid >> 5;
    const int lane = tid & 31;
    const int lr = lane >> 2;         // 0..7  fragment row
    const int lc = lane & 3;          // 0..3  fragment col pair
    const int wm = (wid >> 1) * 64;   // warp M offset
    const int wn = (wid & 1) * 64;    // warp N offset

    int* s_tok = reinterpret_cast<int*>(smem + SM_TOK);
    if (tid < TILE_M) {
        int r = (tid < rows) ? (row0 + tid) : row0;
        s_tok[tid] = g_token_of_row[r];
    }
    __syncthreads();

    // ---- cp.async plan: 16 rows per pass, 8 passes each for A and B ----
    const int seg   = tid & 7;          // 16B piece of the 128B row-chunk
    const int rbase = tid >> 3;         // 0..15
    uint32_t a_src[8];                  // element (half) offsets
#pragma unroll
    for (int j = 0; j < 8; j++)
        a_src[j] = (uint32_t)s_tok[rbase + 16 * j] * KDIM + seg * 8;
    const uint32_t b_src0 = ((uint32_t)e * NDIM + n0 + rbase) * KDIM + seg * 8;
    const uint32_t d0 = (uint32_t)rbase * ROW_BYTES + seg * 16;

    auto load_stage = [&](int ch, int s) {
        const uint32_t abase = sbase + SM_STAGE0 + s * STAGE_BYTES;
        const uint32_t bbase = abase + A_STAGE_BYTES;
        const uint32_t koff = (uint32_t)ch * CHUNK_K;
#pragma unroll
        for (int j = 0; j < 8; j++)
            CP_ASYNC16(abase + d0 + j * (16 * ROW_BYTES), g_xh + a_src[j] + koff);
#pragma unroll
        for (int j = 0; j < 8; j++)
            CP_ASYNC16(bbase + d0 + j * (16 * ROW_BYTES),
                       g_wh + b_src0 + j * (16 * KDIM) + koff);
    };

    // ---- ldmatrix lane-address offsets (within a stage) ----
    // A mf-tile: tiles {rows 0-7 klo, rows 8-15 klo, rows 0-7 khi, rows 8-15 khi}
    //   lane L: row = L&15, byte16 = (L>>4)*16
    uint32_t offA[4];
#pragma unroll
    for (int mf = 0; mf < 4; mf++)
        offA[mf] = (uint32_t)(wm + mf * 16 + (lane & 15)) * ROW_BYTES + (lane >> 4) * 16;
    // B pnf-tile (covers nf=2pnf, 2pnf+1):
    //   tiles {n 0-7 klo, n 0-7 khi, n 8-15 klo, n 8-15 khi}
    //   lane L: n-row = (L>>4)*8 + (L&7), byte16 = ((L>>3)&1)*16
    uint32_t offB[4];
#pragma unroll
    for (int pnf = 0; pnf < 4; pnf++)
        offB[pnf] = (uint32_t)(wn + pnf * 16 + ((lane >> 4) << 3) + (lane & 7)) * ROW_BYTES
                    + ((lane >> 3) & 1) * 16;

    // ---- accumulators: warp tile 64x64 -> 4 mf x 8 nf x 4 regs = 128 ----
    float acc[4][8][4];
#pragma unroll
    for (int mf = 0; mf < 4; mf++)
#pragma unroll
        for (int nf = 0; nf < 8; nf++)
#pragma unroll
            for (int r = 0; r < 4; r++) acc[mf][nf][r] = 0.f;

    load_stage(0, 0); CP_COMMIT();
    load_stage(1, 1); CP_COMMIT();

#pragma unroll 1
    for (int ch = 0; ch < NUM_CHUNKS; ch++) {
        CP_WAIT_1();                 // group for chunk ch has landed
        __syncthreads();

        if (ch + 2 < NUM_CHUNKS) load_stage(ch + 2, (ch + 2) % STAGES);
        CP_COMMIT();

        const uint32_t sA = sbase + SM_STAGE0 + (ch % STAGES) * STAGE_BYTES;
        const uint32_t sB = sA + A_STAGE_BYTES;

#pragma unroll
        for (int kq = 0; kq < 4; kq++) {           // 4 k16 steps per 64-chunk
            const uint32_t ko = kq * 32;           // 16 halves = 32 bytes
            uint32_t fa[4][4];
#pragma unroll
            for (int mf = 0; mf < 4; mf++)
                LDMATRIX_X4(fa[mf], sA + offA[mf] + ko);
            uint32_t fb[4][4];                     // [pnf]: r0,r1 = nf even; r2,r3 = nf odd
#pragma unroll
            for (int pnf = 0; pnf < 4; pnf++)
                LDMATRIX_X4(fb[pnf], sB + offB[pnf] + ko);

#pragma unroll
            for (int mf = 0; mf < 4; mf++)
#pragma unroll
                for (int nf = 0; nf < 8; nf++)
                    mma_f16(acc[mf][nf], fa[mf],
                            fb[nf >> 1][(nf & 1) * 2], fb[nf >> 1][(nf & 1) * 2 + 1]);
        }
    }

    // ---- epilogue: direct float2 stores, mask rows beyond this tile ----
#pragma unroll
    for (int mf = 0; mf < 4; mf++) {
        const int r_lo = wm + mf * 16 + lr;
        const int r_hi = r_lo + 8;
        const bool v_lo = (r_lo < rows);
        const bool v_hi = (r_hi < rows);
        float* o_lo = out + (size_t)(row0 + r_lo) * NDIM + n0;
        float* o_hi = out + (size_t)(row0 + r_hi) * NDIM + n0;
#pragma unroll
        for (int nf = 0; nf < 8; nf++) {
            const int col = wn + nf * 8 + 2 * lc;
            if (v_lo) *reinterpret_cast<float2*>(o_lo + col) =
                make_float2(acc[mf][nf][0], acc[mf][nf][1]);
            if (v_hi) *reinterpret_cast<float2*>(o_hi + col) =
                make_float2(acc[mf][nf][2], acc[mf][nf][3]);
        }
    }
}

// ---------------- launch ------------------------------------------------------
extern "C" void kernel_launch(void* const* d_in, const int* in_sizes, int n_in,
                              void* d_out, int out_size) {
    const float* x       = (const float*)d_in[0];
    const float* w       = (const float*)d_in[1];
    const int*   scatter = (const int*)d_in[2];
    const int*   splits  = (const int*)d_in[3];
    float*       out     = (float*)d_out;
    (void)in_sizes; (void)n_in; (void)out_size;

    cudaFuncSetAttribute(moe_gemm_kernel, cudaFuncAttributeMaxDynamicSharedMemorySize, SMEM_ALLOC);

    const size_t total_groups = ((size_t)NTOKENS * KDIM + (size_t)NEXP * NDIM * KDIM) / 8;
    k_half<<<(int)((total_groups + 255) / 256), 256>>>(x, w);
    k_token<<<(M_OUT + 255) / 256, 256>>>(scatter);
    k_tiles<<<1, 32>>>(splits);

    dim3 grid(MAX_ROW_TILES, N_TILES);
    moe_gemm_kernel<<<grid, THREADS, SMEM_ALLOC>>>(out);
}

// round 12
// speedup vs baseline: 2.1389x; 1.0098x over previous
#include <cuda_runtime.h>
#include <cuda_fp16.h>
#include <cstdint>
#include <cstddef>

// ---------------- problem constants ----------------
#define NTOKENS 8192
#define TOPK    2
#define NEXP    8
#define KDIM    1024
#define NDIM    1024
#define M_OUT   (NTOKENS * TOPK)          // 16384 dispatched rows

#define TILE_M  128
#define TILE_N  128
#define CHUNK_K 64                        // fp16 elems per K chunk = 128B/row
#define NUM_CHUNKS (KDIM / CHUNK_K)       // 16
#define N_TILES (NDIM / TILE_N)           // 8
#define MAX_ROW_TILES 136                 // 16384/128 + NEXP slack
#define THREADS 128
#define STAGES  3

// smem rows padded to 144B -> ldmatrix / cp.async conflict-free
#define ROW_BYTES   144
#define A_STAGE_BYTES (TILE_M * ROW_BYTES)      // 18432
#define B_STAGE_BYTES (TILE_N * ROW_BYTES)      // 18432
#define STAGE_BYTES   (A_STAGE_BYTES + B_STAGE_BYTES)  // 36864
#define SM_TOK    0                              // 128 ints
#define SM_STAGE0 512
#define SMEM_ALLOC (SM_STAGE0 + STAGES * STAGE_BYTES)  // 111104 -> 2 CTAs/SM

// ---------------- PTX helpers (base sm_75/80 ISA; harness targets sm_103 base)
__device__ __forceinline__ uint32_t smem_to_u32(const void* p) {
    uint32_t a;
    asm("{ .reg .u64 t; cvta.to.shared.u64 t, %1; cvt.u32.u64 %0, t; }" : "=r"(a) : "l"(p));
    return a;
}
#define CP_ASYNC16(dst_u32, src_ptr) \
    asm volatile("cp.async.cg.shared.global [%0], [%1], 16;" :: "r"(dst_u32), "l"(src_ptr))
#define CP_COMMIT() asm volatile("cp.async.commit_group;" ::: "memory")
#define CP_WAIT_1() asm volatile("cp.async.wait_group 1;" ::: "memory")

// ldmatrix x4: 4 8x8 b16 tiles; per-lane row address in 'addr'
#define LDMATRIX_X4(r, addr) \
    asm volatile("ldmatrix.sync.aligned.m8n8.x4.shared.b16 {%0,%1,%2,%3}, [%4];" \
                 : "=r"((r)[0]), "=r"((r)[1]), "=r"((r)[2]), "=r"((r)[3]) : "r"(addr))

// mma m16n8k16 fp16 in, fp32 accumulate
__device__ __forceinline__ void mma_f16(float* c, const uint32_t* a, uint32_t b0, uint32_t b1) {
    asm volatile(
        "mma.sync.aligned.m16n8k16.row.col.f32.f16.f16.f32 "
        "{%0,%1,%2,%3}, {%4,%5,%6,%7}, {%8,%9}, {%0,%1,%2,%3};"
        : "+f"(c[0]), "+f"(c[1]), "+f"(c[2]), "+f"(c[3])
        : "r"(a[0]), "r"(a[1]), "r"(a[2]), "r"(a[3]), "r"(b0), "r"(b1));
}

// ---------------- static device scratch (allocation-free rule) --------------
__device__ __half g_xh[(size_t)NTOKENS * KDIM];          // fp16 x, row-major
__device__ __half g_wh[(size_t)NEXP * NDIM * KDIM];      // fp16 W, [e][n][k]
__device__ int g_token_of_row[M_OUT];
__device__ int g_tile_expert[MAX_ROW_TILES];
__device__ int g_tile_row0[MAX_ROW_TILES];
__device__ int g_tile_rows[MAX_ROW_TILES];
__device__ int g_num_tiles;

// ---------------- setup kernels ---------------------------------------------
__device__ __forceinline__ uint32_t pack2(float a, float b) {
    __half2 h = __floats2half2_rn(a, b);
    uint32_t u;
    memcpy(&u, &h, 4);
    return u;
}

__global__ void k_half(const float* __restrict__ x, const float* __restrict__ w) {
    const size_t HALF_GROUPS = (size_t)NTOKENS * KDIM / 8;   // == NEXP*NDIM*KDIM/8
    size_t g = (size_t)blockIdx.x * blockDim.x + threadIdx.x;
    const float* src;
    __half* dst;
    if (g < HALF_GROUPS)          { src = x; dst = g_xh; }
    else if (g < 2 * HALF_GROUPS) { src = w; dst = g_wh; g -= HALF_GROUPS; }
    else return;
    const size_t base = g * 8;
    float4 lo = *reinterpret_cast<const float4*>(src + base);
    float4 hi = *reinterpret_cast<const float4*>(src + base + 4);
    *reinterpret_cast<uint4*>(dst + base) =
        make_uint4(pack2(lo.x, lo.y), pack2(lo.z, lo.w), pack2(hi.x, hi.y), pack2(hi.z, hi.w));
}

__global__ void k_token(const int* __restrict__ scatter) {
    int i = blockIdx.x * blockDim.x + threadIdx.x;
    if (i < M_OUT) g_token_of_row[scatter[i]] = i / TOPK;
}

__global__ void k_tiles(const int* __restrict__ splits) {
    if (threadIdx.x != 0 || blockIdx.x != 0) return;
    int off = 0, t = 0;
    for (int e = 0; e < NEXP; e++) {
        int sc = splits[e];
        for (int m0 = 0; m0 < sc; m0 += TILE_M) {
            g_tile_expert[t] = e;
            g_tile_row0[t]   = off + m0;
            int rr = sc - m0;
            g_tile_rows[t]   = rr < TILE_M ? rr : TILE_M;
            t++;
        }
        off += sc;
    }
    g_num_tiles = t;
}

// ---------------- main grouped-GEMM kernel -----------------------------------
// 128 threads = 4 warps, warp grid 2x2, warp tile 64x64, fp16 m16n8k16. 2 CTAs/SM.
// Inner loop: fragment double-buffering across k16 steps; cp.async burst issued
// in the shadow of the first ldmatrix RAW window.
__global__ void __launch_bounds__(THREADS, 2) moe_gemm_kernel(float* __restrict__ out) {
    extern __shared__ char smem[];
    const uint32_t sbase = smem_to_u32(smem);

    const int row_tile = blockIdx.x;
    if (row_tile >= g_num_tiles) return;
    const int e    = g_tile_expert[row_tile];
    const int row0 = g_tile_row0[row_tile];
    const int rows = g_tile_rows[row_tile];
    const int n0   = blockIdx.y * TILE_N;

    const int tid  = threadIdx.x;
    const int wid  = tid >> 5;
    const int lane = tid & 31;
    const int lr = lane >> 2;         // 0..7  fragment row
    const int lc = lane & 3;          // 0..3  fragment col pair
    const int wm = (wid >> 1) * 64;   // warp M offset
    const int wn = (wid & 1) * 64;    // warp N offset

    int* s_tok = reinterpret_cast<int*>(smem + SM_TOK);
    if (tid < TILE_M) {
        int r = (tid < rows) ? (row0 + tid) : row0;
        s_tok[tid] = g_token_of_row[r];
    }
    __syncthreads();

    // ---- cp.async plan: 16 rows per pass, 8 passes each for A and B ----
    const int seg   = tid & 7;          // 16B piece of the 128B row-chunk
    const int rbase = tid >> 3;         // 0..15
    uint32_t a_src[8];                  // element (half) offsets
#pragma unroll
    for (int j = 0; j < 8; j++)
        a_src[j] = (uint32_t)s_tok[rbase + 16 * j] * KDIM + seg * 8;
    const uint32_t b_src0 = ((uint32_t)e * NDIM + n0 + rbase) * KDIM + seg * 8;
    const uint32_t d0 = (uint32_t)rbase * ROW_BYTES + seg * 16;

    auto load_stage = [&](int ch, int s) {
        const uint32_t abase = sbase + SM_STAGE0 + s * STAGE_BYTES;
        const uint32_t bbase = abase + A_STAGE_BYTES;
        const uint32_t koff = (uint32_t)ch * CHUNK_K;
#pragma unroll
        for (int j = 0; j < 8; j++)
            CP_ASYNC16(abase + d0 + j * (16 * ROW_BYTES), g_xh + a_src[j] + koff);
#pragma unroll
        for (int j = 0; j < 8; j++)
            CP_ASYNC16(bbase + d0 + j * (16 * ROW_BYTES),
                       g_wh + b_src0 + j * (16 * KDIM) + koff);
    };

    // ---- ldmatrix lane-address offsets (within a stage) ----
    uint32_t offA[4];
#pragma unroll
    for (int mf = 0; mf < 4; mf++)
        offA[mf] = (uint32_t)(wm + mf * 16 + (lane & 15)) * ROW_BYTES + (lane >> 4) * 16;
    uint32_t offB[4];
#pragma unroll
    for (int pnf = 0; pnf < 4; pnf++)
        offB[pnf] = (uint32_t)(wn + pnf * 16 + ((lane >> 4) << 3) + (lane & 7)) * ROW_BYTES
                    + ((lane >> 3) & 1) * 16;

    // ---- accumulators: warp tile 64x64 -> 4 mf x 8 nf x 4 regs = 128 ----
    float acc[4][8][4];
#pragma unroll
    for (int mf = 0; mf < 4; mf++)
#pragma unroll
        for (int nf = 0; nf < 8; nf++)
#pragma unroll
            for (int r = 0; r < 4; r++) acc[mf][nf][r] = 0.f;

    load_stage(0, 0); CP_COMMIT();
    load_stage(1, 1); CP_COMMIT();

    // double-buffered fragments
    uint32_t fa[2][4][4];
    uint32_t fb[2][4][4];

#pragma unroll 1
    for (int ch = 0; ch < NUM_CHUNKS; ch++) {
        CP_WAIT_1();                 // group for chunk ch has landed
        __syncthreads();             // all threads' chunk-ch data visible; stage drained

        const uint32_t sA = sbase + SM_STAGE0 + (ch % STAGES) * STAGE_BYTES;
        const uint32_t sB = sA + A_STAGE_BYTES;

        // kq=0 fragments FIRST: their RAW latency shadows the cp.async burst below
#pragma unroll
        for (int mf = 0; mf < 4; mf++)
            LDMATRIX_X4(fa[0][mf], sA + offA[mf]);
#pragma unroll
        for (int pnf = 0; pnf < 4; pnf++)
            LDMATRIX_X4(fb[0][pnf], sB + offB[pnf]);

        if (ch + 2 < NUM_CHUNKS) load_stage(ch + 2, (ch + 2) % STAGES);
        CP_COMMIT();

#pragma unroll
        for (int kq = 0; kq < 4; kq++) {           // 4 k16 steps per 64-chunk
            const int cur = kq & 1, nxt = cur ^ 1;
            if (kq < 3) {                          // prefetch next k16 fragments
                const uint32_t ko = (uint32_t)(kq + 1) * 32;
#pragma unroll
                for (int mf = 0; mf < 4; mf++)
                    LDMATRIX_X4(fa[nxt][mf], sA + offA[mf] + ko);
#pragma unroll
                for (int pnf = 0; pnf < 4; pnf++)
                    LDMATRIX_X4(fb[nxt][pnf], sB + offB[pnf] + ko);
            }
            // 32 independent MMAs cover the prefetch latency
#pragma unroll
            for (int mf = 0; mf < 4; mf++)
#pragma unroll
                for (int nf = 0; nf < 8; nf++)
                    mma_f16(acc[mf][nf], fa[cur][mf],
                            fb[cur][nf >> 1][(nf & 1) * 2], fb[cur][nf >> 1][(nf & 1) * 2 + 1]);
        }
    }

    // ---- epilogue: direct float2 stores, mask rows beyond this tile ----
#pragma unroll
    for (int mf = 0; mf < 4; mf++) {
        const int r_lo = wm + mf * 16 + lr;
        const int r_hi = r_lo + 8;
        const bool v_lo = (r_lo < rows);
        const bool v_hi = (r_hi < rows);
        float* o_lo = out + (size_t)(row0 + r_lo) * NDIM + n0;
        float* o_hi = out + (size_t)(row0 + r_hi) * NDIM + n0;
#pragma unroll
        for (int nf = 0; nf < 8; nf++) {
            const int col = wn + nf * 8 + 2 * lc;
            if (v_lo) *reinterpret_cast<float2*>(o_lo + col) =
                make_float2(acc[mf][nf][0], acc[mf][nf][1]);
            if (v_hi) *reinterpret_cast<float2*>(o_hi + col) =
                make_float2(acc[mf][nf][2], acc[mf][nf][3]);
        }
    }
}

// ---------------- launch ------------------------------------------------------
extern "C" void kernel_launch(void* const* d_in, const int* in_sizes, int n_in,
                              void* d_out, int out_size) {
    const float* x       = (const float*)d_in[0];
    const float* w       = (const float*)d_in[1];
    const int*   scatter = (const int*)d_in[2];
    const int*   splits  = (const int*)d_in[3];
    float*       out     = (float*)d_out;
    (void)in_sizes; (void)n_in; (void)out_size;

    cudaFuncSetAttribute(moe_gemm_kernel, cudaFuncAttributeMaxDynamicSharedMemorySize, SMEM_ALLOC);

    const size_t total_groups = ((size_t)NTOKENS * KDIM + (size_t)NEXP * NDIM * KDIM) / 8;
    k_half<<<(int)((total_groups + 255) / 256), 256>>>(x, w);
    k_token<<<(M_OUT + 255) / 256, 256>>>(scatter);
    k_tiles<<<1, 32>>>(splits);

    dim3 grid(MAX_ROW_TILES, N_TILES);
    moe_gemm_kernel<<<grid, THREADS, SMEM_ALLOC>>>(out);
}

// round 13
// speedup vs baseline: 2.2461x; 1.0501x over previous
#include <cuda_runtime.h>
#include <cuda_fp16.h>
#include <cstdint>
#include <cstddef>

// ---------------- problem constants ----------------
#define NTOKENS 8192
#define TOPK    2
#define NEXP    8
#define KDIM    1024
#define NDIM    1024
#define M_OUT   (NTOKENS * TOPK)          // 16384 dispatched rows

#define TILE_M  64
#define TILE_N  128
#define CHUNK_K 64                        // fp16 elems per K chunk = 128B/row
#define NUM_CHUNKS (KDIM / CHUNK_K)       // 16
#define N_TILES (NDIM / TILE_N)           // 8
#define MAX_ROW_TILES 264                 // 16384/64 + NEXP slack
#define THREADS 128
#define STAGES  2

// smem rows padded to 144B -> ldmatrix / cp.async conflict-free
#define ROW_BYTES   144
#define A_STAGE_BYTES (TILE_M * ROW_BYTES)      // 9216
#define B_STAGE_BYTES (TILE_N * ROW_BYTES)      // 18432
#define STAGE_BYTES   (A_STAGE_BYTES + B_STAGE_BYTES)  // 27648
#define SM_TOK    0                              // 64 ints
#define SM_STAGE0 512
#define SMEM_ALLOC (SM_STAGE0 + STAGES * STAGE_BYTES)  // 55808 -> 4 CTAs/SM

// ---------------- PTX helpers (base sm_75/80 ISA; harness targets sm_103 base)
__device__ __forceinline__ uint32_t smem_to_u32(const void* p) {
    uint32_t a;
    asm("{ .reg .u64 t; cvta.to.shared.u64 t, %1; cvt.u32.u64 %0, t; }" : "=r"(a) : "l"(p));
    return a;
}
#define CP_ASYNC16(dst_u32, src_ptr) \
    asm volatile("cp.async.cg.shared.global [%0], [%1], 16;" :: "r"(dst_u32), "l"(src_ptr))
#define CP_COMMIT() asm volatile("cp.async.commit_group;" ::: "memory")
#define CP_WAIT_1() asm volatile("cp.async.wait_group 1;" ::: "memory")

// ldmatrix x4: 4 8x8 b16 tiles; per-lane row address in 'addr'
#define LDMATRIX_X4(r, addr) \
    asm volatile("ldmatrix.sync.aligned.m8n8.x4.shared.b16 {%0,%1,%2,%3}, [%4];" \
                 : "=r"((r)[0]), "=r"((r)[1]), "=r"((r)[2]), "=r"((r)[3]) : "r"(addr))

// mma m16n8k16 fp16 in, fp32 accumulate
__device__ __forceinline__ void mma_f16(float* c, const uint32_t* a, uint32_t b0, uint32_t b1) {
    asm volatile(
        "mma.sync.aligned.m16n8k16.row.col.f32.f16.f16.f32 "
        "{%0,%1,%2,%3}, {%4,%5,%6,%7}, {%8,%9}, {%0,%1,%2,%3};"
        : "+f"(c[0]), "+f"(c[1]), "+f"(c[2]), "+f"(c[3])
        : "r"(a[0]), "r"(a[1]), "r"(a[2]), "r"(a[3]), "r"(b0), "r"(b1));
}

// ---------------- static device scratch (allocation-free rule) --------------
__device__ __half g_xh[(size_t)NTOKENS * KDIM];          // fp16 x, row-major
__device__ __half g_wh[(size_t)NEXP * NDIM * KDIM];      // fp16 W, [e][n][k]
__device__ int g_token_of_row[M_OUT];
__device__ int g_tile_expert[MAX_ROW_TILES];
__device__ int g_tile_row0[MAX_ROW_TILES];
__device__ int g_tile_rows[MAX_ROW_TILES];
__device__ int g_num_tiles;

// ---------------- setup kernels ---------------------------------------------
__device__ __forceinline__ uint32_t pack2(float a, float b) {
    __half2 h = __floats2half2_rn(a, b);
    uint32_t u;
    memcpy(&u, &h, 4);
    return u;
}

__global__ void k_half(const float* __restrict__ x, const float* __restrict__ w) {
    const size_t HALF_GROUPS = (size_t)NTOKENS * KDIM / 8;   // == NEXP*NDIM*KDIM/8
    size_t g = (size_t)blockIdx.x * blockDim.x + threadIdx.x;
    const float* src;
    __half* dst;
    if (g < HALF_GROUPS)          { src = x; dst = g_xh; }
    else if (g < 2 * HALF_GROUPS) { src = w; dst = g_wh; g -= HALF_GROUPS; }
    else return;
    const size_t base = g * 8;
    float4 lo = *reinterpret_cast<const float4*>(src + base);
    float4 hi = *reinterpret_cast<const float4*>(src + base + 4);
    *reinterpret_cast<uint4*>(dst + base) =
        make_uint4(pack2(lo.x, lo.y), pack2(lo.z, lo.w), pack2(hi.x, hi.y), pack2(hi.z, hi.w));
}

__global__ void k_token(const int* __restrict__ scatter) {
    int i = blockIdx.x * blockDim.x + threadIdx.x;
    if (i < M_OUT) g_token_of_row[scatter[i]] = i / TOPK;
}

__global__ void k_tiles(const int* __restrict__ splits) {
    if (threadIdx.x != 0 || blockIdx.x != 0) return;
    int off = 0, t = 0;
    for (int e = 0; e < NEXP; e++) {
        int sc = splits[e];
        for (int m0 = 0; m0 < sc; m0 += TILE_M) {
            g_tile_expert[t] = e;
            g_tile_row0[t]   = off + m0;
            int rr = sc - m0;
            g_tile_rows[t]   = rr < TILE_M ? rr : TILE_M;
            t++;
        }
        off += sc;
    }
    g_num_tiles = t;
}

// ---------------- main grouped-GEMM kernel -----------------------------------
// CTA 64x128, 4 warps (2x2), warp tile 32x64. 4 CTAs/SM for cross-CTA latency
// hiding. 2-stage cp.async double buffer (2 barriers per chunk).
__global__ void __launch_bounds__(THREADS, 4) moe_gemm_kernel(float* __restrict__ out) {
    extern __shared__ char smem[];
    const uint32_t sbase = smem_to_u32(smem);

    const int row_tile = blockIdx.x;
    if (row_tile >= g_num_tiles) return;
    const int e    = g_tile_expert[row_tile];
    const int row0 = g_tile_row0[row_tile];
    const int rows = g_tile_rows[row_tile];
    const int n0   = blockIdx.y * TILE_N;

    const int tid  = threadIdx.x;
    const int wid  = tid >> 5;
    const int lane = tid & 31;
    const int lr = lane >> 2;         // 0..7  fragment row
    const int lc = lane & 3;          // 0..3  fragment col pair
    const int wm = (wid >> 1) * 32;   // warp M offset (2 rows of warps)
    const int wn = (wid & 1) * 64;    // warp N offset (2 cols of warps)

    int* s_tok = reinterpret_cast<int*>(smem + SM_TOK);
    if (tid < TILE_M) {
        int r = (tid < rows) ? (row0 + tid) : row0;
        s_tok[tid] = g_token_of_row[r];
    }
    __syncthreads();

    // ---- cp.async plan: 16 rows per pass; A 4 passes, B 8 passes ----
    const int seg   = tid & 7;          // 16B piece of the 128B row-chunk
    const int rbase = tid >> 3;         // 0..15
    uint32_t a_src[4];                  // element (half) offsets
#pragma unroll
    for (int j = 0; j < 4; j++)
        a_src[j] = (uint32_t)s_tok[rbase + 16 * j] * KDIM + seg * 8;
    const uint32_t b_src0 = ((uint32_t)e * NDIM + n0 + rbase) * KDIM + seg * 8;
    const uint32_t d0 = (uint32_t)rbase * ROW_BYTES + seg * 16;

    auto load_stage = [&](int ch, int s) {
        const uint32_t abase = sbase + SM_STAGE0 + s * STAGE_BYTES;
        const uint32_t bbase = abase + A_STAGE_BYTES;
        const uint32_t koff = (uint32_t)ch * CHUNK_K;
#pragma unroll
        for (int j = 0; j < 4; j++)
            CP_ASYNC16(abase + d0 + j * (16 * ROW_BYTES), g_xh + a_src[j] + koff);
#pragma unroll
        for (int j = 0; j < 8; j++)
            CP_ASYNC16(bbase + d0 + j * (16 * ROW_BYTES),
                       g_wh + b_src0 + j * (16 * KDIM) + koff);
    };

    // ---- ldmatrix lane-address offsets (within a stage) ----
    uint32_t offA[2];
#pragma unroll
    for (int mf = 0; mf < 2; mf++)
        offA[mf] = (uint32_t)(wm + mf * 16 + (lane & 15)) * ROW_BYTES + (lane >> 4) * 16;
    uint32_t offB[4];
#pragma unroll
    for (int pnf = 0; pnf < 4; pnf++)
        offB[pnf] = (uint32_t)(wn + pnf * 16 + ((lane >> 4) << 3) + (lane & 7)) * ROW_BYTES
                    + ((lane >> 3) & 1) * 16;

    // ---- accumulators: warp tile 32x64 -> 2 mf x 8 nf x 4 regs = 64 ----
    float acc[2][8][4];
#pragma unroll
    for (int mf = 0; mf < 2; mf++)
#pragma unroll
        for (int nf = 0; nf < 8; nf++)
#pragma unroll
            for (int r = 0; r < 4; r++) acc[mf][nf][r] = 0.f;

    load_stage(0, 0); CP_COMMIT();
    load_stage(1, 1); CP_COMMIT();

#pragma unroll 1
    for (int ch = 0; ch < NUM_CHUNKS; ch++) {
        CP_WAIT_1();                 // load(ch) landed (own thread)
        __syncthreads();             // landed for everyone

        const uint32_t sA = sbase + SM_STAGE0 + (ch & 1) * STAGE_BYTES;
        const uint32_t sB = sA + A_STAGE_BYTES;

#pragma unroll
        for (int kq = 0; kq < 4; kq++) {           // 4 k16 steps per 64-chunk
            const uint32_t ko = (uint32_t)kq * 32;
            uint32_t fa[2][4];
#pragma unroll
            for (int mf = 0; mf < 2; mf++)
                LDMATRIX_X4(fa[mf], sA + offA[mf] + ko);
            uint32_t fb[4][4];                     // [pnf]: r0,r1 = nf even; r2,r3 = nf odd
#pragma unroll
            for (int pnf = 0; pnf < 4; pnf++)
                LDMATRIX_X4(fb[pnf], sB + offB[pnf] + ko);

#pragma unroll
            for (int mf = 0; mf < 2; mf++)
#pragma unroll
                for (int nf = 0; nf < 8; nf++)
                    mma_f16(acc[mf][nf], fa[mf],
                            fb[nf >> 1][(nf & 1) * 2], fb[nf >> 1][(nf & 1) * 2 + 1]);
        }

        __syncthreads();             // all warps done reading this stage
        if (ch + 2 < NUM_CHUNKS) load_stage(ch + 2, ch & 1);
        CP_COMMIT();                 // unconditional: keeps group accounting uniform
    }

    // ---- epilogue: direct float2 stores, mask rows beyond this tile ----
#pragma unroll
    for (int mf = 0; mf < 2; mf++) {
        const int r_lo = wm + mf * 16 + lr;
        const int r_hi = r_lo + 8;
        const bool v_lo = (r_lo < rows);
        const bool v_hi = (r_hi < rows);
        float* o_lo = out + (size_t)(row0 + r_lo) * NDIM + n0;
        float* o_hi = out + (size_t)(row0 + r_hi) * NDIM + n0;
#pragma unroll
        for (int nf = 0; nf < 8; nf++) {
            const int col = wn + nf * 8 + 2 * lc;
            if (v_lo) *reinterpret_cast<float2*>(o_lo + col) =
                make_float2(acc[mf][nf][0], acc[mf][nf][1]);
            if (v_hi) *reinterpret_cast<float2*>(o_hi + col) =
                make_float2(acc[mf][nf][2], acc[mf][nf][3]);
        }
    }
}

// ---------------- launch ------------------------------------------------------
extern "C" void kernel_launch(void* const* d_in, const int* in_sizes, int n_in,
                              void* d_out, int out_size) {
    const float* x       = (const float*)d_in[0];
    const float* w       = (const float*)d_in[1];
    const int*   scatter = (const int*)d_in[2];
    const int*   splits  = (const int*)d_in[3];
    float*       out     = (float*)d_out;
    (void)in_sizes; (void)n_in; (void)out_size;

    cudaFuncSetAttribute(moe_gemm_kernel, cudaFuncAttributeMaxDynamicSharedMemorySize, SMEM_ALLOC);

    const size_t total_groups = ((size_t)NTOKENS * KDIM + (size_t)NEXP * NDIM * KDIM) / 8;
    k_half<<<(int)((total_groups + 255) / 256), 256>>>(x, w);
    k_token<<<(M_OUT + 255) / 256, 256>>>(scatter);
    k_tiles<<<1, 32>>>(splits);

    dim3 grid(MAX_ROW_TILES, N_TILES);
    moe_gemm_kernel<<<grid, THREADS, SMEM_ALLOC>>>(out);
}

// round 14
// speedup vs baseline: 2.3027x; 1.0252x over previous
#include <cuda_runtime.h>
#include <cuda_fp16.h>
#include <cstdint>
#include <cstddef>

// ---------------- problem constants ----------------
#define NTOKENS 8192
#define TOPK    2
#define NEXP    8
#define KDIM    1024
#define NDIM    1024
#define M_OUT   (NTOKENS * TOPK)          // 16384 dispatched rows

#define TILE_M  128
#define TILE_N  128
#define CHUNK_K 64                        // fp16 elems per K chunk = 128B/row
#define NUM_CHUNKS (KDIM / CHUNK_K)       // 16
#define N_TILES (NDIM / TILE_N)           // 8
#define MAX_ROW_TILES 136                 // 16384/128 + NEXP slack
#define THREADS 256
#define STAGES  3

// smem rows padded to 144B -> ldmatrix / cp.async conflict-free
#define ROW_BYTES   144
#define A_STAGE_BYTES (TILE_M * ROW_BYTES)      // 18432
#define B_STAGE_BYTES (TILE_N * ROW_BYTES)      // 18432
#define STAGE_BYTES   (A_STAGE_BYTES + B_STAGE_BYTES)  // 36864
#define SM_TOK    0                              // 128 ints
#define SM_STAGE0 512
#define SMEM_ALLOC (SM_STAGE0 + STAGES * STAGE_BYTES)  // 111104 -> 2 CTAs/SM (222KB)

// ---------------- PTX helpers (base sm_75/80 ISA; harness targets sm_103 base)
__device__ __forceinline__ uint32_t smem_to_u32(const void* p) {
    uint32_t a;
    asm("{ .reg .u64 t; cvta.to.shared.u64 t, %1; cvt.u32.u64 %0, t; }" : "=r"(a) : "l"(p));
    return a;
}
#define CP_ASYNC16(dst_u32, src_ptr) \
    asm volatile("cp.async.cg.shared.global [%0], [%1], 16;" :: "r"(dst_u32), "l"(src_ptr))
#define CP_COMMIT() asm volatile("cp.async.commit_group;" ::: "memory")
#define CP_WAIT_1() asm volatile("cp.async.wait_group 1;" ::: "memory")

// ldmatrix x4: 4 8x8 b16 tiles; per-lane row address in 'addr'
#define LDMATRIX_X4(r, addr) \
    asm volatile("ldmatrix.sync.aligned.m8n8.x4.shared.b16 {%0,%1,%2,%3}, [%4];" \
                 : "=r"((r)[0]), "=r"((r)[1]), "=r"((r)[2]), "=r"((r)[3]) : "r"(addr))

// mma m16n8k16 fp16 in, fp32 accumulate
__device__ __forceinline__ void mma_f16(float* c, const uint32_t* a, uint32_t b0, uint32_t b1) {
    asm volatile(
        "mma.sync.aligned.m16n8k16.row.col.f32.f16.f16.f32 "
        "{%0,%1,%2,%3}, {%4,%5,%6,%7}, {%8,%9}, {%0,%1,%2,%3};"
        : "+f"(c[0]), "+f"(c[1]), "+f"(c[2]), "+f"(c[3])
        : "r"(a[0]), "r"(a[1]), "r"(a[2]), "r"(a[3]), "r"(b0), "r"(b1));
}

// ---------------- static device scratch (allocation-free rule) --------------
__device__ __half g_xh[(size_t)NTOKENS * KDIM];          // fp16 x, row-major
__device__ __half g_wh[(size_t)NEXP * NDIM * KDIM];      // fp16 W, [e][n][k]
__device__ int g_token_of_row[M_OUT];
__device__ int g_tile_expert[MAX_ROW_TILES];
__device__ int g_tile_row0[MAX_ROW_TILES];
__device__ int g_tile_rows[MAX_ROW_TILES];
__device__ int g_num_tiles;

// ---------------- setup kernels ---------------------------------------------
__device__ __forceinline__ uint32_t pack2(float a, float b) {
    __half2 h = __floats2half2_rn(a, b);
    uint32_t u;
    memcpy(&u, &h, 4);
    return u;
}

__global__ void k_half(const float* __restrict__ x, const float* __restrict__ w) {
    const size_t HALF_GROUPS = (size_t)NTOKENS * KDIM / 8;   // == NEXP*NDIM*KDIM/8
    size_t g = (size_t)blockIdx.x * blockDim.x + threadIdx.x;
    const float* src;
    __half* dst;
    if (g < HALF_GROUPS)          { src = x; dst = g_xh; }
    else if (g < 2 * HALF_GROUPS) { src = w; dst = g_wh; g -= HALF_GROUPS; }
    else return;
    const size_t base = g * 8;
    float4 lo = *reinterpret_cast<const float4*>(src + base);
    float4 hi = *reinterpret_cast<const float4*>(src + base + 4);
    *reinterpret_cast<uint4*>(dst + base) =
        make_uint4(pack2(lo.x, lo.y), pack2(lo.z, lo.w), pack2(hi.x, hi.y), pack2(hi.z, hi.w));
}

__global__ void k_token(const int* __restrict__ scatter) {
    int i = blockIdx.x * blockDim.x + threadIdx.x;
    if (i < M_OUT) g_token_of_row[scatter[i]] = i / TOPK;
}

__global__ void k_tiles(const int* __restrict__ splits) {
    if (threadIdx.x != 0 || blockIdx.x != 0) return;
    int off = 0, t = 0;
    for (int e = 0; e < NEXP; e++) {
        int sc = splits[e];
        for (int m0 = 0; m0 < sc; m0 += TILE_M) {
            g_tile_expert[t] = e;
            g_tile_row0[t]   = off + m0;
            int rr = sc - m0;
            g_tile_rows[t]   = rr < TILE_M ? rr : TILE_M;
            t++;
        }
        off += sc;
    }
    g_num_tiles = t;
}

// ---------------- main grouped-GEMM kernel -----------------------------------
// CTA 128x128, 256 threads = 8 warps (2 M x 4 N), warp tile 64x32.
// 3-stage cp.async pipeline, ONE barrier per chunk, 2 CTAs/SM (16 warps/SM,
// every SMSP holds warps from both CTAs for cross-CTA latency hiding).
__global__ void __launch_bounds__(THREADS, 2) moe_gemm_kernel(float* __restrict__ out) {
    extern __shared__ char smem[];
    const uint32_t sbase = smem_to_u32(smem);

    const int row_tile = blockIdx.x;
    if (row_tile >= g_num_tiles) return;
    const int e    = g_tile_expert[row_tile];
    const int row0 = g_tile_row0[row_tile];
    const int rows = g_tile_rows[row_tile];
    const int n0   = blockIdx.y * TILE_N;

    const int tid  = threadIdx.x;
    const int wid  = tid >> 5;
    const int lane = tid & 31;
    const int lr = lane >> 2;         // 0..7  fragment row
    const int lc = lane & 3;          // 0..3  fragment col pair
    const int wm = (wid >> 2) * 64;   // warp M offset (2 rows of warps)
    const int wn = (wid & 3) * 32;    // warp N offset (4 cols of warps)

    int* s_tok = reinterpret_cast<int*>(smem + SM_TOK);
    if (tid < TILE_M) {
        int r = (tid < rows) ? (row0 + tid) : row0;
        s_tok[tid] = g_token_of_row[r];
    }
    __syncthreads();

    // ---- cp.async plan: 32 rows per pass, 4 passes each for A and B ----
    const int seg   = tid & 7;          // 16B piece of the 128B row-chunk
    const int rbase = tid >> 3;         // 0..31
    uint32_t a_src[4];                  // element (half) offsets
#pragma unroll
    for (int j = 0; j < 4; j++)
        a_src[j] = (uint32_t)s_tok[rbase + 32 * j] * KDIM + seg * 8;
    const uint32_t b_src0 = ((uint32_t)e * NDIM + n0 + rbase) * KDIM + seg * 8;
    const uint32_t d0 = (uint32_t)rbase * ROW_BYTES + seg * 16;

    auto load_stage = [&](int ch, int s) {
        const uint32_t abase = sbase + SM_STAGE0 + s * STAGE_BYTES;
        const uint32_t bbase = abase + A_STAGE_BYTES;
        const uint32_t koff = (uint32_t)ch * CHUNK_K;
#pragma unroll
        for (int j = 0; j < 4; j++)
            CP_ASYNC16(abase + d0 + j * (32 * ROW_BYTES), g_xh + a_src[j] + koff);
#pragma unroll
        for (int j = 0; j < 4; j++)
            CP_ASYNC16(bbase + d0 + j * (32 * ROW_BYTES),
                       g_wh + b_src0 + j * (32 * KDIM) + koff);
    };

    // ---- ldmatrix lane-address offsets (within a stage) ----
    uint32_t offA[4];
#pragma unroll
    for (int mf = 0; mf < 4; mf++)
        offA[mf] = (uint32_t)(wm + mf * 16 + (lane & 15)) * ROW_BYTES + (lane >> 4) * 16;
    uint32_t offB[2];
#pragma unroll
    for (int pnf = 0; pnf < 2; pnf++)
        offB[pnf] = (uint32_t)(wn + pnf * 16 + ((lane >> 4) << 3) + (lane & 7)) * ROW_BYTES
                    + ((lane >> 3) & 1) * 16;

    // ---- accumulators: warp tile 64x32 -> 4 mf x 4 nf x 4 regs = 64 ----
    float acc[4][4][4];
#pragma unroll
    for (int mf = 0; mf < 4; mf++)
#pragma unroll
        for (int nf = 0; nf < 4; nf++)
#pragma unroll
            for (int r = 0; r < 4; r++) acc[mf][nf][r] = 0.f;

    load_stage(0, 0); CP_COMMIT();
    load_stage(1, 1); CP_COMMIT();

#pragma unroll 1
    for (int ch = 0; ch < NUM_CHUNKS; ch++) {
        CP_WAIT_1();                 // load(ch) landed (own thread's groups)
        __syncthreads();             // landed for everyone; stage (ch+2)%3 drained

        // refill the stage all warps finished reading last iteration
        if (ch + 2 < NUM_CHUNKS) load_stage(ch + 2, (ch + 2) % STAGES);
        CP_COMMIT();

        const uint32_t sA = sbase + SM_STAGE0 + (ch % STAGES) * STAGE_BYTES;
        const uint32_t sB = sA + A_STAGE_BYTES;

#pragma unroll
        for (int kq = 0; kq < 4; kq++) {           // 4 k16 steps per 64-chunk
            const uint32_t ko = (uint32_t)kq * 32;
            uint32_t fa[4][4];
#pragma unroll
            for (int mf = 0; mf < 4; mf++)
                LDMATRIX_X4(fa[mf], sA + offA[mf] + ko);
            uint32_t fb[2][4];                     // [pnf]: r0,r1 = nf even; r2,r3 = nf odd
#pragma unroll
            for (int pnf = 0; pnf < 2; pnf++)
                LDMATRIX_X4(fb[pnf], sB + offB[pnf] + ko);

#pragma unroll
            for (int mf = 0; mf < 4; mf++)
#pragma unroll
                for (int nf = 0; nf < 4; nf++)
                    mma_f16(acc[mf][nf], fa[mf],
                            fb[nf >> 1][(nf & 1) * 2], fb[nf >> 1][(nf & 1) * 2 + 1]);
        }
    }

    // ---- epilogue: direct float2 stores, mask rows beyond this tile ----
#pragma unroll
    for (int mf = 0; mf < 4; mf++) {
        const int r_lo = wm + mf * 16 + lr;
        const int r_hi = r_lo + 8;
        const bool v_lo = (r_lo < rows);
        const bool v_hi = (r_hi < rows);
        float* o_lo = out + (size_t)(row0 + r_lo) * NDIM + n0;
        float* o_hi = out + (size_t)(row0 + r_hi) * NDIM + n0;
#pragma unroll
        for (int nf = 0; nf < 4; nf++) {
            const int col = wn + nf * 8 + 2 * lc;
            if (v_lo) *reinterpret_cast<float2*>(o_lo + col) =
                make_float2(acc[mf][nf][0], acc[mf][nf][1]);
            if (v_hi) *reinterpret_cast<float2*>(o_hi + col) =
                make_float2(acc[mf][nf][2], acc[mf][nf][3]);
        }
    }
}

// ---------------- launch ------------------------------------------------------
extern "C" void kernel_launch(void* const* d_in, const int* in_sizes, int n_in,
                              void* d_out, int out_size) {
    const float* x       = (const float*)d_in[0];
    const float* w       = (const float*)d_in[1];
    const int*   scatter = (const int*)d_in[2];
    const int*   splits  = (const int*)d_in[3];
    float*       out     = (float*)d_out;
    (void)in_sizes; (void)n_in; (void)out_size;

    cudaFuncSetAttribute(moe_gemm_kernel, cudaFuncAttributeMaxDynamicSharedMemorySize, SMEM_ALLOC);

    const size_t total_groups = ((size_t)NTOKENS * KDIM + (size_t)NEXP * NDIM * KDIM) / 8;
    k_half<<<(int)((total_groups + 255) / 256), 256>>>(x, w);
    k_token<<<(M_OUT + 255) / 256, 256>>>(scatter);
    k_tiles<<<1, 32>>>(splits);

    dim3 grid(MAX_ROW_TILES, N_TILES);
    moe_gemm_kernel<<<grid, THREADS, SMEM_ALLOC>>>(out);
}